// round 2
// baseline (speedup 1.0000x reference)
#include <cuda_runtime.h>

// ============================================================================
// RNN_29463475650831: GRU(T=11,F=3,H=11, reset_after) + Dense(121->7) + softmax
// B = 1,048,576. fp32 everywhere. Strategy: 4 batch elements per thread as
// 2x f32x2 packed lanes; weights pre-duplicated (w,w) in smem; fused dense.
// ============================================================================

#define NTHREADS 256
#define VP 2            // f32x2 pairs per thread (=> 4 elements per thread)
#define B_TOTAL 1048576
#define LOG2E 1.4426950408889634f

typedef unsigned long long p2;   // packed f32x2

// Duplicated/rearranged weights:
//  region A: j-blocks, 48 p2 per j (11 j):   [bzc, brc, bih, brh, Kz*3, Kr*3, Kh*3, Rz*11, Rr*11, Rh*11, pad2]
//  region D: dense, 8 p2 per (t,j) (121):    [Wd[t*11+j][0..6], pad]
//  region Db: dense bias: 8 p2
// total = 528 + 968 + 8 = 1504 p2 = 12032 bytes
#define WTOT 1504
__device__ __align__(16) float2 g_wdup[WTOT];

// ---------------- f32x2 helpers ----------------
static __device__ __forceinline__ p2 pk2(float lo, float hi) {
    p2 r; asm("mov.b64 %0, {%1, %2};" : "=l"(r) : "f"(lo), "f"(hi)); return r;
}
static __device__ __forceinline__ void up2(p2 a, float& lo, float& hi) {
    asm("mov.b64 {%0, %1}, %2;" : "=f"(lo), "=f"(hi) : "l"(a));
}
static __device__ __forceinline__ p2 ffma2(p2 a, p2 b, p2 c) {
    p2 d; asm("fma.rn.f32x2 %0, %1, %2, %3;" : "=l"(d) : "l"(a), "l"(b), "l"(c)); return d;
}
static __device__ __forceinline__ p2 fmul2(p2 a, p2 b) {
    p2 d; asm("mul.rn.f32x2 %0, %1, %2;" : "=l"(d) : "l"(a), "l"(b)); return d;
}
static __device__ __forceinline__ float fex2(float x) {
    float y; asm("ex2.approx.f32 %0, %1;" : "=f"(y) : "f"(x)); return y;
}
static __device__ __forceinline__ float frcp(float x) {
    float y; asm("rcp.approx.f32 %0, %1;" : "=f"(y) : "f"(x)); return y;
}

// sigmoid(x) = rcp(1 + 2^(-x*log2e)).  Saturates correctly at +/-inf.
static __device__ __forceinline__ p2 sig2(p2 a) {
    p2 t = fmul2(a, pk2(-LOG2E, -LOG2E));
    float lo, hi; up2(t, lo, hi);
    lo = frcp(1.0f + fex2(lo));
    hi = frcp(1.0f + fex2(hi));
    return pk2(lo, hi);
}
// tanh(x) = 1 - 2*rcp(1 + 2^(2x*log2e)).  Saturates correctly at +/-inf.
static __device__ __forceinline__ p2 tnh2(p2 a) {
    p2 t = fmul2(a, pk2(2.0f * LOG2E, 2.0f * LOG2E));
    float lo, hi; up2(t, lo, hi);
    lo = frcp(1.0f + fex2(lo));
    hi = frcp(1.0f + fex2(hi));
    return ffma2(pk2(lo, hi), pk2(-2.0f, -2.0f), pk2(1.0f, 1.0f));
}

// ---------------- prologue: rearrange + duplicate weights ----------------
__global__ void prep_kernel(const float* __restrict__ K,      // [3, 33]
                            const float* __restrict__ R,      // [11, 33]
                            const float* __restrict__ bias,   // [2, 33]
                            const float* __restrict__ Wd,     // [121, 7]
                            const float* __restrict__ db) {   // [7]
    int i = blockIdx.x * blockDim.x + threadIdx.x;
    if (i >= WTOT) return;
    float v = 0.0f;
    if (i < 528) {
        int j = i / 48, k = i % 48;
        if      (k == 0)  v = bias[j]       + bias[33 + j];        // z: in_b + rec_b
        else if (k == 1)  v = bias[11 + j]  + bias[44 + j];        // r: in_b + rec_b
        else if (k == 2)  v = bias[22 + j];                        // h: in_b
        else if (k == 3)  v = bias[55 + j];                        // h: rec_b
        else if (k < 7)   v = K[(k - 4)  * 33 + j];                // Kz
        else if (k < 10)  v = K[(k - 7)  * 33 + 11 + j];           // Kr
        else if (k < 13)  v = K[(k - 10) * 33 + 22 + j];           // Kh
        else if (k < 24)  v = R[(k - 13) * 33 + j];                // Rz
        else if (k < 35)  v = R[(k - 24) * 33 + 11 + j];           // Rr
        else if (k < 46)  v = R[(k - 35) * 33 + 22 + j];           // Rh
    } else if (i < 1496) {
        int d = i - 528;
        int tj = d / 8, c = d % 8;
        if (c < 7) v = Wd[tj * 7 + c];
    } else {
        int c = i - 1496;
        if (c < 7) v = db[c];
    }
    g_wdup[i] = make_float2(v, v);
}

// ---------------- main kernel ----------------
__global__ __launch_bounds__(NTHREADS, 1)
void gru_main(const float* __restrict__ x, float* __restrict__ out) {
    __shared__ __align__(16) p2 ws[WTOT];
    {
        const float4* s = reinterpret_cast<const float4*>(g_wdup);
        float4* d = reinterpret_cast<float4*>(ws);
        #pragma unroll 4
        for (int i = threadIdx.x; i < WTOT / 2; i += NTHREADS) d[i] = s[i];
    }
    __syncthreads();

    const int tid = blockIdx.x * NTHREADS + threadIdx.x;
    const float* xp = x + (size_t)tid * (4u * 33u);   // 4 elements, 33 floats each

    p2 h[VP][11];
    #pragma unroll
    for (int v = 0; v < VP; v++)
        #pragma unroll
        for (int i = 0; i < 11; i++) h[v][i] = 0ULL;

    p2 acc[VP][7];
    #pragma unroll
    for (int v = 0; v < VP; v++)
        #pragma unroll
        for (int c = 0; c < 7; c++) acc[v][c] = ws[1496 + c];

    #pragma unroll 1
    for (int t = 0; t < 11; t++) {
        // load x[t] for the 4 elements, packed pairwise
        p2 xt[VP][3];
        #pragma unroll
        for (int v = 0; v < VP; v++)
            #pragma unroll
            for (int f = 0; f < 3; f++)
                xt[v][f] = pk2(xp[(2 * v) * 33 + t * 3 + f],
                               xp[(2 * v + 1) * 33 + t * 3 + f]);

        p2 hn[VP][11];
        const p2* wd = ws + 528 + t * 88;

        #pragma unroll
        for (int j = 0; j < 11; j++) {
            const p2* W = ws + j * 48;
            p2 az[VP], ar[VP], ah[VP], bh[VP];
            #pragma unroll
            for (int v = 0; v < VP; v++) {
                az[v] = W[0]; ar[v] = W[1]; ah[v] = W[2]; bh[v] = W[3];
            }
            #pragma unroll
            for (int f = 0; f < 3; f++)
                #pragma unroll
                for (int v = 0; v < VP; v++) {
                    az[v] = ffma2(xt[v][f], W[4 + f],  az[v]);
                    ar[v] = ffma2(xt[v][f], W[7 + f],  ar[v]);
                    ah[v] = ffma2(xt[v][f], W[10 + f], ah[v]);
                }
            #pragma unroll
            for (int i = 0; i < 11; i++)
                #pragma unroll
                for (int v = 0; v < VP; v++) {
                    az[v] = ffma2(h[v][i], W[13 + i], az[v]);
                    ar[v] = ffma2(h[v][i], W[24 + i], ar[v]);
                    bh[v] = ffma2(h[v][i], W[35 + i], bh[v]);
                }
            const p2* wj = wd + j * 8;
            #pragma unroll
            for (int v = 0; v < VP; v++) {
                p2 z  = sig2(az[v]);
                p2 r  = sig2(ar[v]);
                p2 hh = tnh2(ffma2(r, bh[v], ah[v]));
                p2 dd = ffma2(hh, pk2(-1.0f, -1.0f), h[v][j]);  // h - hh
                p2 nh = ffma2(z, dd, hh);                       // hh + z*(h-hh)
                hn[v][j] = nh;
                #pragma unroll
                for (int c = 0; c < 7; c++)
                    acc[v][c] = ffma2(nh, wj[c], acc[v][c]);    // fused dense
            }
        }
        #pragma unroll
        for (int v = 0; v < VP; v++)
            #pragma unroll
            for (int i = 0; i < 11; i++) h[v][i] = hn[v][i];
    }

    // softmax per element + store
    #pragma unroll
    for (int v = 0; v < VP; v++) {
        float l0[7], l1[7];
        #pragma unroll
        for (int c = 0; c < 7; c++) up2(acc[v][c], l0[c], l1[c]);
        const size_t e0 = (size_t)tid * 4 + 2 * v;
        {
            float m = l0[0];
            #pragma unroll
            for (int c = 1; c < 7; c++) m = fmaxf(m, l0[c]);
            float e[7], s = 0.0f;
            #pragma unroll
            for (int c = 0; c < 7; c++) { e[c] = fex2((l0[c] - m) * LOG2E); s += e[c]; }
            float inv = frcp(s);
            #pragma unroll
            for (int c = 0; c < 7; c++) out[e0 * 7 + c] = e[c] * inv;
        }
        {
            float m = l1[0];
            #pragma unroll
            for (int c = 1; c < 7; c++) m = fmaxf(m, l1[c]);
            float e[7], s = 0.0f;
            #pragma unroll
            for (int c = 0; c < 7; c++) { e[c] = fex2((l1[c] - m) * LOG2E); s += e[c]; }
            float inv = frcp(s);
            #pragma unroll
            for (int c = 0; c < 7; c++) out[(e0 + 1) * 7 + c] = e[c] * inv;
        }
    }
}

// ---------------- launch ----------------
extern "C" void kernel_launch(void* const* d_in, const int* in_sizes, int n_in,
                              void* d_out, int out_size) {
    const float* x    = (const float*)d_in[0];   // [B, 11, 3]
    const float* K    = (const float*)d_in[1];   // [3, 33]
    const float* R    = (const float*)d_in[2];   // [11, 33]
    const float* bias = (const float*)d_in[3];   // [2, 33]
    const float* Wd   = (const float*)d_in[4];   // [121, 7]
    const float* db   = (const float*)d_in[5];   // [7]
    float* out = (float*)d_out;                  // [B, 7]

    prep_kernel<<<(WTOT + 255) / 256, 256>>>(K, R, bias, Wd, db);

    const int threads_total = B_TOTAL / 4;       // 4 elements per thread
    gru_main<<<threads_total / NTHREADS, NTHREADS>>>(x, out);
}

// round 3
// speedup vs baseline: 1.0876x; 1.0876x over previous
#include <cuda_runtime.h>

// ============================================================================
// RNN_29463475650831: GRU(T=11,F=3,H=11, reset_after) + Dense(121->7) + softmax
// B = 1,048,576. fp32. R2: VP=1 (2 elems/thread as one f32x2 lane), reg-capped
// at 2 blocks/SM, x transposed to coalesced plane layout in a prologue.
// ============================================================================

#define NTHREADS 256
#define B_TOTAL 1048576
#define PAIRS (B_TOTAL / 2)          // 524288 element-pairs
#define LOG2E 1.4426950408889634f

typedef unsigned long long p2;       // packed f32x2

// Duplicated/rearranged weights (see prep_kernel):
//  region A: j-blocks, 48 p2 per j (11 j)
//  region D: dense, 8 p2 per (t,j) (121 blocks)
//  region Db: dense bias: 8 p2
#define WTOT 1504
__device__ __align__(16) float2 g_wdup[WTOT];

// Transposed input: plane layout [t*3+f][pair], each entry = (x[2p], x[2p+1])
__device__ __align__(16) p2 g_xT[33u * PAIRS];   // 138 MB static scratch

// ---------------- f32x2 helpers ----------------
static __device__ __forceinline__ p2 pk2(float lo, float hi) {
    p2 r; asm("mov.b64 %0, {%1, %2};" : "=l"(r) : "f"(lo), "f"(hi)); return r;
}
static __device__ __forceinline__ void up2(p2 a, float& lo, float& hi) {
    asm("mov.b64 {%0, %1}, %2;" : "=f"(lo), "=f"(hi) : "l"(a));
}
static __device__ __forceinline__ p2 ffma2(p2 a, p2 b, p2 c) {
    p2 d; asm("fma.rn.f32x2 %0, %1, %2, %3;" : "=l"(d) : "l"(a), "l"(b), "l"(c)); return d;
}
static __device__ __forceinline__ p2 fmul2(p2 a, p2 b) {
    p2 d; asm("mul.rn.f32x2 %0, %1, %2;" : "=l"(d) : "l"(a), "l"(b)); return d;
}
static __device__ __forceinline__ float fex2(float x) {
    float y; asm("ex2.approx.f32 %0, %1;" : "=f"(y) : "f"(x)); return y;
}
static __device__ __forceinline__ float frcp(float x) {
    float y; asm("rcp.approx.f32 %0, %1;" : "=f"(y) : "f"(x)); return y;
}

// sigmoid(x) = rcp(1 + 2^(-x*log2e))
static __device__ __forceinline__ p2 sig2(p2 a) {
    p2 t = fmul2(a, pk2(-LOG2E, -LOG2E));
    float lo, hi; up2(t, lo, hi);
    lo = frcp(1.0f + fex2(lo));
    hi = frcp(1.0f + fex2(hi));
    return pk2(lo, hi);
}
// tanh(x) = 1 - 2*rcp(1 + 2^(2x*log2e))
static __device__ __forceinline__ p2 tnh2(p2 a) {
    p2 t = fmul2(a, pk2(2.0f * LOG2E, 2.0f * LOG2E));
    float lo, hi; up2(t, lo, hi);
    lo = frcp(1.0f + fex2(lo));
    hi = frcp(1.0f + fex2(hi));
    return ffma2(pk2(lo, hi), pk2(-2.0f, -2.0f), pk2(1.0f, 1.0f));
}

// ---------------- prologue 1: rearrange + duplicate weights ----------------
__global__ void prep_kernel(const float* __restrict__ K,      // [3, 33]
                            const float* __restrict__ R,      // [11, 33]
                            const float* __restrict__ bias,   // [2, 33]
                            const float* __restrict__ Wd,     // [121, 7]
                            const float* __restrict__ db) {   // [7]
    int i = blockIdx.x * blockDim.x + threadIdx.x;
    if (i >= WTOT) return;
    float v = 0.0f;
    if (i < 528) {
        int j = i / 48, k = i % 48;
        if      (k == 0)  v = bias[j]       + bias[33 + j];        // z: in+rec
        else if (k == 1)  v = bias[11 + j]  + bias[44 + j];        // r: in+rec
        else if (k == 2)  v = bias[22 + j];                        // h: in
        else if (k == 3)  v = bias[55 + j];                        // h: rec
        else if (k < 7)   v = K[(k - 4)  * 33 + j];                // Kz
        else if (k < 10)  v = K[(k - 7)  * 33 + 11 + j];           // Kr
        else if (k < 13)  v = K[(k - 10) * 33 + 22 + j];           // Kh
        else if (k < 24)  v = R[(k - 13) * 33 + j];                // Rz
        else if (k < 35)  v = R[(k - 24) * 33 + 11 + j];           // Rr
        else if (k < 46)  v = R[(k - 35) * 33 + 22 + j];           // Rh
    } else if (i < 1496) {
        int d = i - 528;
        int tj = d / 8, c = d % 8;
        if (c < 7) v = Wd[tj * 7 + c];
    } else {
        int c = i - 1496;
        if (c < 7) v = db[c];
    }
    g_wdup[i] = make_float2(v, v);
}

// ---------------- prologue 2: transpose x to plane layout ----------------
// Block handles 256 consecutive elements: coalesced read of 256*33 floats,
// then writes 33 planes of 128 float2 pairs each (coalesced within plane).
#define TP_ELEMS 256
__global__ __launch_bounds__(256)
void xpose_kernel(const float* __restrict__ x) {
    __shared__ float tile[TP_ELEMS * 33];
    const unsigned base = blockIdx.x * (TP_ELEMS * 33u);
    #pragma unroll
    for (int k = 0; k < 33; k++) {
        int i = k * 256 + threadIdx.x;
        tile[i] = x[base + i];
    }
    __syncthreads();
    float2* xt = reinterpret_cast<float2*>(g_xT);
    const unsigned pbase = blockIdx.x * (TP_ELEMS / 2);   // pair base
    #pragma unroll 4
    for (int idx = threadIdx.x; idx < 33 * (TP_ELEMS / 2); idx += 256) {
        int plane = idx / (TP_ELEMS / 2);
        int pr    = idx % (TP_ELEMS / 2);
        float lo = tile[(2 * pr)     * 33 + plane];
        float hi = tile[(2 * pr + 1) * 33 + plane];
        xt[(size_t)plane * PAIRS + pbase + pr] = make_float2(lo, hi);
    }
}

// ---------------- main kernel ----------------
__global__ __launch_bounds__(NTHREADS, 2)
void gru_main(float* __restrict__ out) {
    __shared__ __align__(16) p2 ws[WTOT];
    {
        const float4* s = reinterpret_cast<const float4*>(g_wdup);
        float4* d = reinterpret_cast<float4*>(ws);
        #pragma unroll 4
        for (int i = threadIdx.x; i < WTOT / 2; i += NTHREADS) d[i] = s[i];
    }
    __syncthreads();

    const unsigned p = blockIdx.x * NTHREADS + threadIdx.x;   // pair index

    p2 h[11];
    #pragma unroll
    for (int i = 0; i < 11; i++) h[i] = 0ULL;

    p2 acc[7];
    #pragma unroll
    for (int c = 0; c < 7; c++) acc[c] = ws[1496 + c];

    #pragma unroll 1
    for (int t = 0; t < 11; t++) {
        // coalesced x loads: 3 LDG.64 per step
        p2 xt[3];
        #pragma unroll
        for (int f = 0; f < 3; f++)
            xt[f] = g_xT[(size_t)(t * 3 + f) * PAIRS + p];

        p2 hn[11];
        const p2* wd = ws + 528 + t * 88;

        #pragma unroll
        for (int j = 0; j < 11; j++) {
            const p2* W = ws + j * 48;
            p2 az = W[0], ar = W[1], ah = W[2], bh = W[3];
            #pragma unroll
            for (int f = 0; f < 3; f++) {
                az = ffma2(xt[f], W[4 + f],  az);
                ar = ffma2(xt[f], W[7 + f],  ar);
                ah = ffma2(xt[f], W[10 + f], ah);
            }
            #pragma unroll
            for (int i = 0; i < 11; i++) {
                az = ffma2(h[i], W[13 + i], az);
                ar = ffma2(h[i], W[24 + i], ar);
                bh = ffma2(h[i], W[35 + i], bh);
            }
            p2 z  = sig2(az);
            p2 r  = sig2(ar);
            p2 hh = tnh2(ffma2(r, bh, ah));
            p2 dd = ffma2(hh, pk2(-1.0f, -1.0f), h[j]);   // h - hh
            p2 nh = ffma2(z, dd, hh);                     // hh + z*(h-hh)
            hn[j] = nh;
            const p2* wj = wd + j * 8;
            #pragma unroll
            for (int c = 0; c < 7; c++)
                acc[c] = ffma2(nh, wj[c], acc[c]);        // fused dense
        }
        #pragma unroll
        for (int i = 0; i < 11; i++) h[i] = hn[i];
    }

    // softmax for both elements of the pair + store
    float l0[7], l1[7];
    #pragma unroll
    for (int c = 0; c < 7; c++) up2(acc[c], l0[c], l1[c]);
    const size_t e0 = (size_t)p * 2;
    {
        float m = l0[0];
        #pragma unroll
        for (int c = 1; c < 7; c++) m = fmaxf(m, l0[c]);
        float e[7], s = 0.0f;
        #pragma unroll
        for (int c = 0; c < 7; c++) { e[c] = fex2((l0[c] - m) * LOG2E); s += e[c]; }
        float inv = frcp(s);
        #pragma unroll
        for (int c = 0; c < 7; c++) out[e0 * 7 + c] = e[c] * inv;
    }
    {
        float m = l1[0];
        #pragma unroll
        for (int c = 1; c < 7; c++) m = fmaxf(m, l1[c]);
        float e[7], s = 0.0f;
        #pragma unroll
        for (int c = 0; c < 7; c++) { e[c] = fex2((l1[c] - m) * LOG2E); s += e[c]; }
        float inv = frcp(s);
        #pragma unroll
        for (int c = 0; c < 7; c++) out[(e0 + 1) * 7 + c] = e[c] * inv;
    }
}

// ---------------- launch ----------------
extern "C" void kernel_launch(void* const* d_in, const int* in_sizes, int n_in,
                              void* d_out, int out_size) {
    const float* x    = (const float*)d_in[0];   // [B, 11, 3]
    const float* K    = (const float*)d_in[1];   // [3, 33]
    const float* R    = (const float*)d_in[2];   // [11, 33]
    const float* bias = (const float*)d_in[3];   // [2, 33]
    const float* Wd   = (const float*)d_in[4];   // [121, 7]
    const float* db   = (const float*)d_in[5];   // [7]
    float* out = (float*)d_out;                  // [B, 7]

    prep_kernel<<<(WTOT + 255) / 256, 256>>>(K, R, bias, Wd, db);
    xpose_kernel<<<B_TOTAL / TP_ELEMS, 256>>>(x);
    gru_main<<<PAIRS / NTHREADS, NTHREADS>>>(out);
}

// round 4
// speedup vs baseline: 1.1433x; 1.0512x over previous
#include <cuda_runtime.h>

// ============================================================================
// RNN_29463475650831: GRU(T=11,F=3,H=11, reset_after) + Dense(121->7) + softmax
// B = 1,048,576. fp32. R4: pair-packed smem weights (LDS.128), x prefetch,
// 2-kernel pipeline (xpose+prep fused), float2 stores.
// ============================================================================

#define NTHREADS 128
#define B_TOTAL 1048576
#define PAIRS (B_TOTAL / 2)          // 524288 element-pairs
#define LOG2E 1.4426950408889634f

typedef unsigned long long p2;       // packed f32x2

// Paired/duplicated weight image (p2 entries, each = (w,w)):
// region A: 48 p2 per j (11 j):
//   0:bz 1:br 2:bh_in 3:bh_rec
//   4..9:  (Kz[f],Kr[f]) f=0..2 interleaved
//   10..12: Kh[0..2]  13: pad
//   14..35: (Rz[i],Rr[i]) i=0..10 interleaved
//   36..46: Rh[0..10] 47: pad
// region D (base 528): 8 p2 per (t,j): w[0..6], pad
// region Db (base 1496): dense bias [7], pad
#define WTOT 1504
__device__ __align__(16) float2 g_wdup[WTOT];

// Transposed input: plane layout [t*3+f][pair], entry = (x[2p], x[2p+1])
__device__ __align__(16) p2 g_xT[33u * PAIRS];   // 138 MB static scratch

// ---------------- f32x2 helpers ----------------
static __device__ __forceinline__ p2 pk2(float lo, float hi) {
    p2 r; asm("mov.b64 %0, {%1, %2};" : "=l"(r) : "f"(lo), "f"(hi)); return r;
}
static __device__ __forceinline__ void up2(p2 a, float& lo, float& hi) {
    asm("mov.b64 {%0, %1}, %2;" : "=f"(lo), "=f"(hi) : "l"(a));
}
static __device__ __forceinline__ p2 ffma2(p2 a, p2 b, p2 c) {
    p2 d; asm("fma.rn.f32x2 %0, %1, %2, %3;" : "=l"(d) : "l"(a), "l"(b), "l"(c)); return d;
}
static __device__ __forceinline__ p2 fmul2(p2 a, p2 b) {
    p2 d; asm("mul.rn.f32x2 %0, %1, %2;" : "=l"(d) : "l"(a), "l"(b)); return d;
}
static __device__ __forceinline__ float fex2(float x) {
    float y; asm("ex2.approx.f32 %0, %1;" : "=f"(y) : "f"(x)); return y;
}
static __device__ __forceinline__ float frcp(float x) {
    float y; asm("rcp.approx.f32 %0, %1;" : "=f"(y) : "f"(x)); return y;
}

// sigmoid(x) = rcp(1 + 2^(-x*log2e))
static __device__ __forceinline__ p2 sig2(p2 a) {
    p2 t = fmul2(a, pk2(-LOG2E, -LOG2E));
    float lo, hi; up2(t, lo, hi);
    lo = frcp(1.0f + fex2(lo));
    hi = frcp(1.0f + fex2(hi));
    return pk2(lo, hi);
}
// tanh(x) = 1 - 2*rcp(1 + 2^(2x*log2e))
static __device__ __forceinline__ p2 tnh2(p2 a) {
    p2 t = fmul2(a, pk2(2.0f * LOG2E, 2.0f * LOG2E));
    float lo, hi; up2(t, lo, hi);
    lo = frcp(1.0f + fex2(lo));
    hi = frcp(1.0f + fex2(hi));
    return ffma2(pk2(lo, hi), pk2(-2.0f, -2.0f), pk2(1.0f, 1.0f));
}

// ---------------- weight image builder (device helper) ----------------
static __device__ __forceinline__ float wval(int i,
                                             const float* K, const float* R,
                                             const float* bias, const float* Wd,
                                             const float* db) {
    float v = 0.0f;
    if (i < 528) {
        int j = i / 48, k = i % 48;
        if      (k == 0)  v = bias[j]      + bias[33 + j];
        else if (k == 1)  v = bias[11 + j] + bias[44 + j];
        else if (k == 2)  v = bias[22 + j];
        else if (k == 3)  v = bias[55 + j];
        else if (k < 10) { int f = (k - 4) >> 1;
                           v = ((k & 1) == 0) ? K[f * 33 + j] : K[f * 33 + 11 + j]; }
        else if (k < 13)  v = K[(k - 10) * 33 + 22 + j];
        else if (k == 13) v = 0.0f;
        else if (k < 36) { int q = (k - 14) >> 1;
                           v = ((k & 1) == 0) ? R[q * 33 + j] : R[q * 33 + 11 + j]; }
        else if (k < 47)  v = R[(k - 36) * 33 + 22 + j];
    } else if (i < 1496) {
        int d = i - 528, c = d & 7;
        if (c < 7) v = Wd[(d >> 3) * 7 + c];
    } else {
        int c = i - 1496;
        if (c < 7) v = db[c];
    }
    return v;
}

// ---------------- kernel 1: transpose x + (block 0) build weight image ------
#define TP_ELEMS 256
__global__ __launch_bounds__(256)
void xpose_kernel(const float* __restrict__ x,
                  const float* __restrict__ K, const float* __restrict__ R,
                  const float* __restrict__ bias, const float* __restrict__ Wd,
                  const float* __restrict__ db) {
    __shared__ float tile[TP_ELEMS * 33];
    const unsigned base = blockIdx.x * (TP_ELEMS * 33u);
    #pragma unroll
    for (int k = 0; k < 33; k++) {
        int i = k * 256 + threadIdx.x;
        tile[i] = x[base + i];
    }
    if (blockIdx.x == 0) {
        for (int i = threadIdx.x; i < WTOT; i += 256) {
            float v = wval(i, K, R, bias, Wd, db);
            g_wdup[i] = make_float2(v, v);
        }
    }
    __syncthreads();
    float2* xt = reinterpret_cast<float2*>(g_xT);
    const unsigned pbase = blockIdx.x * (TP_ELEMS / 2);
    #pragma unroll 4
    for (int idx = threadIdx.x; idx < 33 * (TP_ELEMS / 2); idx += 256) {
        int plane = idx / (TP_ELEMS / 2);
        int pr    = idx % (TP_ELEMS / 2);
        float lo = tile[(2 * pr)     * 33 + plane];
        float hi = tile[(2 * pr + 1) * 33 + plane];
        xt[(size_t)plane * PAIRS + pbase + pr] = make_float2(lo, hi);
    }
}

// ---------------- kernel 2: main GRU ----------------
__global__ __launch_bounds__(NTHREADS, 4)
void gru_main(float* __restrict__ out) {
    __shared__ __align__(16) p2 ws[WTOT];
    {
        const float4* s = reinterpret_cast<const float4*>(g_wdup);
        float4* d = reinterpret_cast<float4*>(ws);
        #pragma unroll 4
        for (int i = threadIdx.x; i < WTOT / 2; i += NTHREADS) d[i] = s[i];
    }
    __syncthreads();

    const unsigned p = blockIdx.x * NTHREADS + threadIdx.x;   // pair index

    p2 h[11];
    #pragma unroll
    for (int i = 0; i < 11; i++) h[i] = 0ULL;

    p2 acc[7];
    #pragma unroll
    for (int c = 0; c < 7; c++) acc[c] = ws[1496 + c];

    // prefetched x for current step
    p2 xc[3];
    #pragma unroll
    for (int f = 0; f < 3; f++) xc[f] = g_xT[(size_t)f * PAIRS + p];

    #pragma unroll 1
    for (int t = 0; t < 11; t++) {
        // prefetch next step's x (harmless reload of t=10 on last iter)
        const int tn = (t < 10) ? (t + 1) : 10;
        p2 xn[3];
        #pragma unroll
        for (int f = 0; f < 3; f++)
            xn[f] = g_xT[(size_t)(tn * 3 + f) * PAIRS + p];

        p2 hn[11];
        const p2* wd = ws + 528 + t * 88;

        #pragma unroll
        for (int j = 0; j < 11; j++) {
            const ulonglong2* W = reinterpret_cast<const ulonglong2*>(ws + j * 48);
            ulonglong2 u;
            u = W[0];  p2 az = u.x, ar = u.y;
            u = W[1];  p2 ah = u.x, bh = u.y;
            u = W[2];  az = ffma2(xc[0], u.x, az); ar = ffma2(xc[0], u.y, ar);
            u = W[3];  az = ffma2(xc[1], u.x, az); ar = ffma2(xc[1], u.y, ar);
            u = W[4];  az = ffma2(xc[2], u.x, az); ar = ffma2(xc[2], u.y, ar);
            u = W[5];  ah = ffma2(xc[0], u.x, ah); ah = ffma2(xc[1], u.y, ah);
            u = W[6];  ah = ffma2(xc[2], u.x, ah);
            #pragma unroll
            for (int i = 0; i < 11; i++) {
                u = W[7 + i];
                az = ffma2(h[i], u.x, az);
                ar = ffma2(h[i], u.y, ar);
            }
            #pragma unroll
            for (int k = 0; k < 5; k++) {
                u = W[18 + k];
                bh = ffma2(h[2 * k], u.x, bh);
                bh = ffma2(h[2 * k + 1], u.y, bh);
            }
            u = W[23]; bh = ffma2(h[10], u.x, bh);

            p2 z  = sig2(az);
            p2 r  = sig2(ar);
            p2 hh = tnh2(ffma2(r, bh, ah));
            p2 dd = ffma2(hh, pk2(-1.0f, -1.0f), h[j]);   // h - hh
            p2 nh = ffma2(z, dd, hh);                     // hh + z*(h-hh)
            hn[j] = nh;

            const ulonglong2* wj = reinterpret_cast<const ulonglong2*>(wd + j * 8);
            u = wj[0]; acc[0] = ffma2(nh, u.x, acc[0]); acc[1] = ffma2(nh, u.y, acc[1]);
            u = wj[1]; acc[2] = ffma2(nh, u.x, acc[2]); acc[3] = ffma2(nh, u.y, acc[3]);
            u = wj[2]; acc[4] = ffma2(nh, u.x, acc[4]); acc[5] = ffma2(nh, u.y, acc[5]);
            u = wj[3]; acc[6] = ffma2(nh, u.x, acc[6]);
        }
        #pragma unroll
        for (int i = 0; i < 11; i++) h[i] = hn[i];
        #pragma unroll
        for (int f = 0; f < 3; f++) xc[f] = xn[f];
    }

    // softmax for both elements of the pair; write as float2 (coalesced-ish)
    float l0[7], l1[7];
    #pragma unroll
    for (int c = 0; c < 7; c++) up2(acc[c], l0[c], l1[c]);

    float r14[14];
    {
        float m = l0[0];
        #pragma unroll
        for (int c = 1; c < 7; c++) m = fmaxf(m, l0[c]);
        float e[7], s = 0.0f;
        #pragma unroll
        for (int c = 0; c < 7; c++) { e[c] = fex2((l0[c] - m) * LOG2E); s += e[c]; }
        float inv = frcp(s);
        #pragma unroll
        for (int c = 0; c < 7; c++) r14[c] = e[c] * inv;
    }
    {
        float m = l1[0];
        #pragma unroll
        for (int c = 1; c < 7; c++) m = fmaxf(m, l1[c]);
        float e[7], s = 0.0f;
        #pragma unroll
        for (int c = 0; c < 7; c++) { e[c] = fex2((l1[c] - m) * LOG2E); s += e[c]; }
        float inv = frcp(s);
        #pragma unroll
        for (int c = 0; c < 7; c++) r14[7 + c] = e[c] * inv;
    }
    float2* out2 = reinterpret_cast<float2*>(out) + (size_t)p * 7;  // 56B/pair, 8B aligned
    #pragma unroll
    for (int q = 0; q < 7; q++) out2[q] = make_float2(r14[2 * q], r14[2 * q + 1]);
}

// ---------------- launch ----------------
extern "C" void kernel_launch(void* const* d_in, const int* in_sizes, int n_in,
                              void* d_out, int out_size) {
    const float* x    = (const float*)d_in[0];   // [B, 11, 3]
    const float* K    = (const float*)d_in[1];   // [3, 33]
    const float* R    = (const float*)d_in[2];   // [11, 33]
    const float* bias = (const float*)d_in[3];   // [2, 33]
    const float* Wd   = (const float*)d_in[4];   // [121, 7]
    const float* db   = (const float*)d_in[5];   // [7]
    float* out = (float*)d_out;                  // [B, 7]

    xpose_kernel<<<B_TOTAL / TP_ELEMS, 256>>>(x, K, R, bias, Wd, db);
    gru_main<<<PAIRS / NTHREADS, NTHREADS>>>(out);
}

// round 5
// speedup vs baseline: 1.1516x; 1.0073x over previous
#include <cuda_runtime.h>

// ============================================================================
// RNN_29463475650831: GRU(T=11,F=3,H=11, reset_after) + Dense(121->7) + softmax
// B = 1,048,576. fp32. R5: spill elimination — 168-reg budget (3 blocks/SM),
// no x prefetch. Pair-packed smem weights (LDS.128), f32x2 datapath.
// ============================================================================

#define NTHREADS 128
#define B_TOTAL 1048576
#define PAIRS (B_TOTAL / 2)          // 524288 element-pairs
#define LOG2E 1.4426950408889634f

typedef unsigned long long p2;       // packed f32x2

// Paired/duplicated weight image (p2 entries, each = (w,w)):
// region A: 48 p2 per j (11 j):
//   0:bz 1:br 2:bh_in 3:bh_rec
//   4..9:  (Kz[f],Kr[f]) f=0..2 interleaved
//   10..12: Kh[0..2]  13: pad
//   14..35: (Rz[i],Rr[i]) i=0..10 interleaved
//   36..46: Rh[0..10] 47: pad
// region D (base 528): 8 p2 per (t,j): w[0..6], pad
// region Db (base 1496): dense bias [7], pad
#define WTOT 1504
__device__ __align__(16) float2 g_wdup[WTOT];

// Transposed input: plane layout [t*3+f][pair], entry = (x[2p], x[2p+1])
__device__ __align__(16) p2 g_xT[33u * PAIRS];   // 138 MB static scratch

// ---------------- f32x2 helpers ----------------
static __device__ __forceinline__ p2 pk2(float lo, float hi) {
    p2 r; asm("mov.b64 %0, {%1, %2};" : "=l"(r) : "f"(lo), "f"(hi)); return r;
}
static __device__ __forceinline__ void up2(p2 a, float& lo, float& hi) {
    asm("mov.b64 {%0, %1}, %2;" : "=f"(lo), "=f"(hi) : "l"(a));
}
static __device__ __forceinline__ p2 ffma2(p2 a, p2 b, p2 c) {
    p2 d; asm("fma.rn.f32x2 %0, %1, %2, %3;" : "=l"(d) : "l"(a), "l"(b), "l"(c)); return d;
}
static __device__ __forceinline__ p2 fmul2(p2 a, p2 b) {
    p2 d; asm("mul.rn.f32x2 %0, %1, %2;" : "=l"(d) : "l"(a), "l"(b)); return d;
}
static __device__ __forceinline__ float fex2(float x) {
    float y; asm("ex2.approx.f32 %0, %1;" : "=f"(y) : "f"(x)); return y;
}
static __device__ __forceinline__ float frcp(float x) {
    float y; asm("rcp.approx.f32 %0, %1;" : "=f"(y) : "f"(x)); return y;
}

// sigmoid(x) = rcp(1 + 2^(-x*log2e))
static __device__ __forceinline__ p2 sig2(p2 a) {
    p2 t = fmul2(a, pk2(-LOG2E, -LOG2E));
    float lo, hi; up2(t, lo, hi);
    lo = frcp(1.0f + fex2(lo));
    hi = frcp(1.0f + fex2(hi));
    return pk2(lo, hi);
}
// tanh(x) = 1 - 2*rcp(1 + 2^(2x*log2e))
static __device__ __forceinline__ p2 tnh2(p2 a) {
    p2 t = fmul2(a, pk2(2.0f * LOG2E, 2.0f * LOG2E));
    float lo, hi; up2(t, lo, hi);
    lo = frcp(1.0f + fex2(lo));
    hi = frcp(1.0f + fex2(hi));
    return ffma2(pk2(lo, hi), pk2(-2.0f, -2.0f), pk2(1.0f, 1.0f));
}

// ---------------- weight image builder (device helper) ----------------
static __device__ __forceinline__ float wval(int i,
                                             const float* K, const float* R,
                                             const float* bias, const float* Wd,
                                             const float* db) {
    float v = 0.0f;
    if (i < 528) {
        int j = i / 48, k = i % 48;
        if      (k == 0)  v = bias[j]      + bias[33 + j];
        else if (k == 1)  v = bias[11 + j] + bias[44 + j];
        else if (k == 2)  v = bias[22 + j];
        else if (k == 3)  v = bias[55 + j];
        else if (k < 10) { int f = (k - 4) >> 1;
                           v = ((k & 1) == 0) ? K[f * 33 + j] : K[f * 33 + 11 + j]; }
        else if (k < 13)  v = K[(k - 10) * 33 + 22 + j];
        else if (k == 13) v = 0.0f;
        else if (k < 36) { int q = (k - 14) >> 1;
                           v = ((k & 1) == 0) ? R[q * 33 + j] : R[q * 33 + 11 + j]; }
        else if (k < 47)  v = R[(k - 36) * 33 + 22 + j];
    } else if (i < 1496) {
        int d = i - 528, c = d & 7;
        if (c < 7) v = Wd[(d >> 3) * 7 + c];
    } else {
        int c = i - 1496;
        if (c < 7) v = db[c];
    }
    return v;
}

// ---------------- kernel 1: transpose x + (block 0) build weight image ------
#define TP_ELEMS 256
__global__ __launch_bounds__(256)
void xpose_kernel(const float* __restrict__ x,
                  const float* __restrict__ K, const float* __restrict__ R,
                  const float* __restrict__ bias, const float* __restrict__ Wd,
                  const float* __restrict__ db) {
    __shared__ float tile[TP_ELEMS * 33];
    const unsigned base = blockIdx.x * (TP_ELEMS * 33u);
    #pragma unroll
    for (int k = 0; k < 33; k++) {
        int i = k * 256 + threadIdx.x;
        tile[i] = x[base + i];
    }
    if (blockIdx.x == 0) {
        for (int i = threadIdx.x; i < WTOT; i += 256) {
            float v = wval(i, K, R, bias, Wd, db);
            g_wdup[i] = make_float2(v, v);
        }
    }
    __syncthreads();
    float2* xt = reinterpret_cast<float2*>(g_xT);
    const unsigned pbase = blockIdx.x * (TP_ELEMS / 2);
    #pragma unroll 4
    for (int idx = threadIdx.x; idx < 33 * (TP_ELEMS / 2); idx += 256) {
        int plane = idx / (TP_ELEMS / 2);
        int pr    = idx % (TP_ELEMS / 2);
        float lo = tile[(2 * pr)     * 33 + plane];
        float hi = tile[(2 * pr + 1) * 33 + plane];
        xt[(size_t)plane * PAIRS + pbase + pr] = make_float2(lo, hi);
    }
}

// ---------------- kernel 2: main GRU ----------------
__global__ __launch_bounds__(NTHREADS, 3)   // 168-reg budget: NO spills
void gru_main(float* __restrict__ out) {
    __shared__ __align__(16) p2 ws[WTOT];
    {
        const float4* s = reinterpret_cast<const float4*>(g_wdup);
        float4* d = reinterpret_cast<float4*>(ws);
        #pragma unroll 4
        for (int i = threadIdx.x; i < WTOT / 2; i += NTHREADS) d[i] = s[i];
    }
    __syncthreads();

    const unsigned p = blockIdx.x * NTHREADS + threadIdx.x;   // pair index

    p2 h[11];
    #pragma unroll
    for (int i = 0; i < 11; i++) h[i] = 0ULL;

    p2 acc[7];
    #pragma unroll
    for (int c = 0; c < 7; c++) acc[c] = ws[1496 + c];

    #pragma unroll 1
    for (int t = 0; t < 11; t++) {
        // coalesced x loads for this step (3 LDG.64; issued up front)
        p2 xc[3];
        #pragma unroll
        for (int f = 0; f < 3; f++)
            xc[f] = g_xT[(size_t)(t * 3 + f) * PAIRS + p];

        p2 hn[11];
        const p2* wd = ws + 528 + t * 88;

        #pragma unroll
        for (int j = 0; j < 11; j++) {
            const ulonglong2* W = reinterpret_cast<const ulonglong2*>(ws + j * 48);
            ulonglong2 u;
            u = W[0];  p2 az = u.x, ar = u.y;
            u = W[1];  p2 ah = u.x, bh = u.y;
            u = W[2];  az = ffma2(xc[0], u.x, az); ar = ffma2(xc[0], u.y, ar);
            u = W[3];  az = ffma2(xc[1], u.x, az); ar = ffma2(xc[1], u.y, ar);
            u = W[4];  az = ffma2(xc[2], u.x, az); ar = ffma2(xc[2], u.y, ar);
            u = W[5];  ah = ffma2(xc[0], u.x, ah); ah = ffma2(xc[1], u.y, ah);
            u = W[6];  ah = ffma2(xc[2], u.x, ah);
            #pragma unroll
            for (int i = 0; i < 11; i++) {
                u = W[7 + i];
                az = ffma2(h[i], u.x, az);
                ar = ffma2(h[i], u.y, ar);
            }
            #pragma unroll
            for (int k = 0; k < 5; k++) {
                u = W[18 + k];
                bh = ffma2(h[2 * k], u.x, bh);
                bh = ffma2(h[2 * k + 1], u.y, bh);
            }
            u = W[23]; bh = ffma2(h[10], u.x, bh);

            p2 z  = sig2(az);
            p2 r  = sig2(ar);
            p2 hh = tnh2(ffma2(r, bh, ah));
            p2 dd = ffma2(hh, pk2(-1.0f, -1.0f), h[j]);   // h - hh
            p2 nh = ffma2(z, dd, hh);                     // hh + z*(h-hh)
            hn[j] = nh;

            const ulonglong2* wj = reinterpret_cast<const ulonglong2*>(wd + j * 8);
            u = wj[0]; acc[0] = ffma2(nh, u.x, acc[0]); acc[1] = ffma2(nh, u.y, acc[1]);
            u = wj[1]; acc[2] = ffma2(nh, u.x, acc[2]); acc[3] = ffma2(nh, u.y, acc[3]);
            u = wj[2]; acc[4] = ffma2(nh, u.x, acc[4]); acc[5] = ffma2(nh, u.y, acc[5]);
            u = wj[3]; acc[6] = ffma2(nh, u.x, acc[6]);
        }
        #pragma unroll
        for (int i = 0; i < 11; i++) h[i] = hn[i];
    }

    // softmax for both elements of the pair; float2 stores
    float l0[7], l1[7];
    #pragma unroll
    for (int c = 0; c < 7; c++) up2(acc[c], l0[c], l1[c]);

    float r14[14];
    {
        float m = l0[0];
        #pragma unroll
        for (int c = 1; c < 7; c++) m = fmaxf(m, l0[c]);
        float e[7], s = 0.0f;
        #pragma unroll
        for (int c = 0; c < 7; c++) { e[c] = fex2((l0[c] - m) * LOG2E); s += e[c]; }
        float inv = frcp(s);
        #pragma unroll
        for (int c = 0; c < 7; c++) r14[c] = e[c] * inv;
    }
    {
        float m = l1[0];
        #pragma unroll
        for (int c = 1; c < 7; c++) m = fmaxf(m, l1[c]);
        float e[7], s = 0.0f;
        #pragma unroll
        for (int c = 0; c < 7; c++) { e[c] = fex2((l1[c] - m) * LOG2E); s += e[c]; }
        float inv = frcp(s);
        #pragma unroll
        for (int c = 0; c < 7; c++) r14[7 + c] = e[c] * inv;
    }
    float2* out2 = reinterpret_cast<float2*>(out) + (size_t)p * 7;  // 56B/pair
    #pragma unroll
    for (int q = 0; q < 7; q++) out2[q] = make_float2(r14[2 * q], r14[2 * q + 1]);
}

// ---------------- launch ----------------
extern "C" void kernel_launch(void* const* d_in, const int* in_sizes, int n_in,
                              void* d_out, int out_size) {
    const float* x    = (const float*)d_in[0];   // [B, 11, 3]
    const float* K    = (const float*)d_in[1];   // [3, 33]
    const float* R    = (const float*)d_in[2];   // [11, 33]
    const float* bias = (const float*)d_in[3];   // [2, 33]
    const float* Wd   = (const float*)d_in[4];   // [121, 7]
    const float* db   = (const float*)d_in[5];   // [7]
    float* out = (float*)d_out;                  // [B, 7]

    xpose_kernel<<<B_TOTAL / TP_ELEMS, 256>>>(x, K, R, bias, Wd, db);
    gru_main<<<PAIRS / NTHREADS, NTHREADS>>>(out);
}

// round 6
// speedup vs baseline: 1.3188x; 1.1451x over previous
#include <cuda_runtime.h>

// ============================================================================
// RNN_29463475650831: GRU(T=11,F=3,H=11, reset_after) + Dense(121->7) + softmax
// B = 1,048,576. fp32. R6: SCALAR datapath (1 element/thread) — the f32x2
// register-pair arrays were forcing ptxas to spill ~44KB/thread to local,
// making every prior version DRAM-bound on spill traffic.
// ============================================================================

#define NTHREADS 128
#define B_TOTAL 1048576
#define LOG2E 1.4426950408889634f

// Scalar weight image (floats):
// region A: 48 floats per j (11 j):
//   0:bz(in+rec) 1:br(in+rec) 2:bh_in 3:bh_rec
//   4..6: Kz   7..9: Kr   10..12: Kh   13: pad
//   14..24: Rz 25..35: Rr 36..46: Rh   47: pad
// region D (base 528): 8 floats per (t,j): Wd[t*11+j][0..6], pad
// region Db (base 1496): dense bias [7], pad   -> total 1504 floats = 6 KB
#define WTOTF 1504
__device__ __align__(16) float g_wimg[WTOTF];

// Transposed input: plane layout [t*3+f][elem]  (33 planes of B floats)
__device__ __align__(16) float g_xT[33u * B_TOTAL];   // 138 MB static scratch

// ---------------- scalar math helpers ----------------
static __device__ __forceinline__ float fex2(float x) {
    float y; asm("ex2.approx.f32 %0, %1;" : "=f"(y) : "f"(x)); return y;
}
static __device__ __forceinline__ float frcp(float x) {
    float y; asm("rcp.approx.f32 %0, %1;" : "=f"(y) : "f"(x)); return y;
}
static __device__ __forceinline__ float sig1(float a) {
    return frcp(1.0f + fex2(-LOG2E * a));     // sigmoid
}
static __device__ __forceinline__ float tnh1(float a) {
    return 1.0f - 2.0f * frcp(1.0f + fex2(2.0f * LOG2E * a));   // tanh
}

// ---------------- weight image builder ----------------
static __device__ __forceinline__ float wval(int i,
                                             const float* K, const float* R,
                                             const float* bias, const float* Wd,
                                             const float* db) {
    float v = 0.0f;
    if (i < 528) {
        int j = i / 48, k = i % 48;
        if      (k == 0)  v = bias[j]      + bias[33 + j];
        else if (k == 1)  v = bias[11 + j] + bias[44 + j];
        else if (k == 2)  v = bias[22 + j];
        else if (k == 3)  v = bias[55 + j];
        else if (k < 7)   v = K[(k - 4)  * 33 + j];
        else if (k < 10)  v = K[(k - 7)  * 33 + 11 + j];
        else if (k < 13)  v = K[(k - 10) * 33 + 22 + j];
        else if (k == 13) v = 0.0f;
        else if (k < 25)  v = R[(k - 14) * 33 + j];
        else if (k < 36)  v = R[(k - 25) * 33 + 11 + j];
        else if (k < 47)  v = R[(k - 36) * 33 + 22 + j];
    } else if (i < 1496) {
        int d = i - 528, c = d & 7;
        if (c < 7) v = Wd[(d >> 3) * 7 + c];
    } else {
        int c = i - 1496;
        if (c < 7) v = db[c];
    }
    return v;
}

// ---------------- kernel 1: transpose x + (block 0) build weight image ------
#define TP_ELEMS 256
__global__ __launch_bounds__(256)
void xpose_kernel(const float* __restrict__ x,
                  const float* __restrict__ K, const float* __restrict__ R,
                  const float* __restrict__ bias, const float* __restrict__ Wd,
                  const float* __restrict__ db) {
    __shared__ float tile[TP_ELEMS * 33];
    const unsigned base = blockIdx.x * (TP_ELEMS * 33u);
    #pragma unroll
    for (int k = 0; k < 33; k++) {
        int i = k * 256 + threadIdx.x;
        tile[i] = x[base + i];
    }
    if (blockIdx.x == 0) {
        for (int i = threadIdx.x; i < WTOTF; i += 256) {
            g_wimg[i] = wval(i, K, R, bias, Wd, db);
        }
    }
    __syncthreads();
    const unsigned ebase = blockIdx.x * TP_ELEMS;
    #pragma unroll 4
    for (int idx = threadIdx.x; idx < 33 * TP_ELEMS; idx += 256) {
        int plane = idx / TP_ELEMS;          // 0..32
        int el    = idx % TP_ELEMS;          // 0..255 -> coalesced write
        g_xT[(size_t)plane * B_TOTAL + ebase + el] = tile[el * 33 + plane];
    }
}

// ---------------- kernel 2: main GRU (scalar) ----------------
__global__ __launch_bounds__(NTHREADS, 5)   // 102-reg budget
void gru_main(float* __restrict__ out) {
    __shared__ __align__(16) float ws[WTOTF];
    {
        const float4* s = reinterpret_cast<const float4*>(g_wimg);
        float4* d = reinterpret_cast<float4*>(ws);
        #pragma unroll
        for (int i = threadIdx.x; i < WTOTF / 4; i += NTHREADS) d[i] = s[i];
    }
    __syncthreads();

    const unsigned e = blockIdx.x * NTHREADS + threadIdx.x;   // element index

    float h[11];
    #pragma unroll
    for (int i = 0; i < 11; i++) h[i] = 0.0f;

    float acc[7];
    #pragma unroll
    for (int c = 0; c < 7; c++) acc[c] = ws[1496 + c];

    #pragma unroll 1
    for (int t = 0; t < 11; t++) {
        // coalesced x loads (3 LDG.32 per step)
        const float x0 = g_xT[(size_t)(t * 3 + 0) * B_TOTAL + e];
        const float x1 = g_xT[(size_t)(t * 3 + 1) * B_TOTAL + e];
        const float x2 = g_xT[(size_t)(t * 3 + 2) * B_TOTAL + e];

        float hn[11];
        const float* wd = ws + 528 + t * 88;

        #pragma unroll
        for (int j = 0; j < 11; j++) {
            const float* W = ws + j * 48;
            float az = W[0], ar = W[1], ah = W[2], bh = W[3];
            az = fmaf(x0, W[4],  az); az = fmaf(x1, W[5],  az); az = fmaf(x2, W[6],  az);
            ar = fmaf(x0, W[7],  ar); ar = fmaf(x1, W[8],  ar); ar = fmaf(x2, W[9],  ar);
            ah = fmaf(x0, W[10], ah); ah = fmaf(x1, W[11], ah); ah = fmaf(x2, W[12], ah);
            #pragma unroll
            for (int i = 0; i < 11; i++) {
                az = fmaf(h[i], W[14 + i], az);
                ar = fmaf(h[i], W[25 + i], ar);
                bh = fmaf(h[i], W[36 + i], bh);
            }
            float z  = sig1(az);
            float r  = sig1(ar);
            float hh = tnh1(fmaf(r, bh, ah));
            float nh = fmaf(z, h[j] - hh, hh);          // hh + z*(h-hh)
            hn[j] = nh;

            const float* wj = wd + j * 8;
            #pragma unroll
            for (int c = 0; c < 7; c++)
                acc[c] = fmaf(nh, wj[c], acc[c]);       // fused dense
        }
        #pragma unroll
        for (int i = 0; i < 11; i++) h[i] = hn[i];
    }

    // softmax + store
    float m = acc[0];
    #pragma unroll
    for (int c = 1; c < 7; c++) m = fmaxf(m, acc[c]);
    float ex[7], s = 0.0f;
    #pragma unroll
    for (int c = 0; c < 7; c++) { ex[c] = fex2((acc[c] - m) * LOG2E); s += ex[c]; }
    const float inv = frcp(s);
    float* o = out + (size_t)e * 7;
    #pragma unroll
    for (int c = 0; c < 7; c++) o[c] = ex[c] * inv;
}

// ---------------- launch ----------------
extern "C" void kernel_launch(void* const* d_in, const int* in_sizes, int n_in,
                              void* d_out, int out_size) {
    const float* x    = (const float*)d_in[0];   // [B, 11, 3]
    const float* K    = (const float*)d_in[1];   // [3, 33]
    const float* R    = (const float*)d_in[2];   // [11, 33]
    const float* bias = (const float*)d_in[3];   // [2, 33]
    const float* Wd   = (const float*)d_in[4];   // [121, 7]
    const float* db   = (const float*)d_in[5];   // [7]
    float* out = (float*)d_out;                  // [B, 7]

    xpose_kernel<<<B_TOTAL / TP_ELEMS, 256>>>(x, K, R, bias, Wd, db);
    gru_main<<<B_TOTAL / NTHREADS, NTHREADS>>>(out);
}

// round 7
// speedup vs baseline: 2.8166x; 2.1358x over previous
#include <cuda_runtime.h>

// ============================================================================
// RNN_29463475650831: GRU(T=11,F=3,H=11, reset_after) + Dense(121->7) + softmax
// B = 1,048,576. fp32. R7: scalar datapath + 168-reg budget (128thr x 3 blk/SM).
// Diagnosis: all prior rounds were spill-bound; reg caps below ptxas's pressure
// peak (LDS batching across the 11-way unrolled j-loop) forced ~17GB of local
// DRAM traffic. Scalar state + generous cap = headroom above the peak.
// ============================================================================

#define NTHREADS 128
#define B_TOTAL 1048576
#define LOG2E 1.4426950408889634f

// Scalar weight image (floats):
// region A: 48 floats per j (11 j):
//   0:bz(in+rec) 1:br(in+rec) 2:bh_in 3:bh_rec
//   4..6: Kz   7..9: Kr   10..12: Kh   13: pad
//   14..24: Rz 25..35: Rr 36..46: Rh   47: pad
// region D (base 528): 8 floats per (t,j): Wd[t*11+j][0..6], pad
// region Db (base 1496): dense bias [7], pad   -> total 1504 floats = 6 KB
#define WTOTF 1504
__device__ __align__(16) float g_wimg[WTOTF];

// Transposed input: plane layout [t*3+f][elem]  (33 planes of B floats)
__device__ __align__(16) float g_xT[33u * B_TOTAL];   // 138 MB static scratch

// ---------------- scalar math helpers ----------------
static __device__ __forceinline__ float fex2(float x) {
    float y; asm("ex2.approx.f32 %0, %1;" : "=f"(y) : "f"(x)); return y;
}
static __device__ __forceinline__ float frcp(float x) {
    float y; asm("rcp.approx.f32 %0, %1;" : "=f"(y) : "f"(x)); return y;
}
static __device__ __forceinline__ float sig1(float a) {
    return frcp(1.0f + fex2(-LOG2E * a));     // sigmoid
}
static __device__ __forceinline__ float tnh1(float a) {
    return 1.0f - 2.0f * frcp(1.0f + fex2(2.0f * LOG2E * a));   // tanh
}

// ---------------- weight image builder ----------------
static __device__ __forceinline__ float wval(int i,
                                             const float* K, const float* R,
                                             const float* bias, const float* Wd,
                                             const float* db) {
    float v = 0.0f;
    if (i < 528) {
        int j = i / 48, k = i % 48;
        if      (k == 0)  v = bias[j]      + bias[33 + j];
        else if (k == 1)  v = bias[11 + j] + bias[44 + j];
        else if (k == 2)  v = bias[22 + j];
        else if (k == 3)  v = bias[55 + j];
        else if (k < 7)   v = K[(k - 4)  * 33 + j];
        else if (k < 10)  v = K[(k - 7)  * 33 + 11 + j];
        else if (k < 13)  v = K[(k - 10) * 33 + 22 + j];
        else if (k == 13) v = 0.0f;
        else if (k < 25)  v = R[(k - 14) * 33 + j];
        else if (k < 36)  v = R[(k - 25) * 33 + 11 + j];
        else if (k < 47)  v = R[(k - 36) * 33 + 22 + j];
    } else if (i < 1496) {
        int d = i - 528, c = d & 7;
        if (c < 7) v = Wd[(d >> 3) * 7 + c];
    } else {
        int c = i - 1496;
        if (c < 7) v = db[c];
    }
    return v;
}

// ---------------- kernel 1: transpose x + (block 0) build weight image ------
#define TP_ELEMS 256
__global__ __launch_bounds__(256)
void xpose_kernel(const float* __restrict__ x,
                  const float* __restrict__ K, const float* __restrict__ R,
                  const float* __restrict__ bias, const float* __restrict__ Wd,
                  const float* __restrict__ db) {
    __shared__ float tile[TP_ELEMS * 33];
    const unsigned base = blockIdx.x * (TP_ELEMS * 33u);
    #pragma unroll
    for (int k = 0; k < 33; k++) {
        int i = k * 256 + threadIdx.x;
        tile[i] = x[base + i];
    }
    if (blockIdx.x == 0) {
        for (int i = threadIdx.x; i < WTOTF; i += 256) {
            g_wimg[i] = wval(i, K, R, bias, Wd, db);
        }
    }
    __syncthreads();
    const unsigned ebase = blockIdx.x * TP_ELEMS;
    #pragma unroll 4
    for (int idx = threadIdx.x; idx < 33 * TP_ELEMS; idx += 256) {
        int plane = idx / TP_ELEMS;          // 0..32
        int el    = idx % TP_ELEMS;          // 0..255 -> coalesced write
        g_xT[(size_t)plane * B_TOTAL + ebase + el] = tile[el * 33 + plane];
    }
}

// ---------------- kernel 2: main GRU (scalar, 168-reg budget) ----------------
__global__ __launch_bounds__(NTHREADS, 3)   // 168 regs/thread available
void gru_main(float* __restrict__ out) {
    __shared__ __align__(16) float ws[WTOTF];
    {
        const float4* s = reinterpret_cast<const float4*>(g_wimg);
        float4* d = reinterpret_cast<float4*>(ws);
        #pragma unroll
        for (int i = threadIdx.x; i < WTOTF / 4; i += NTHREADS) d[i] = s[i];
    }
    __syncthreads();

    const unsigned e = blockIdx.x * NTHREADS + threadIdx.x;   // element index

    float h[11];
    #pragma unroll
    for (int i = 0; i < 11; i++) h[i] = 0.0f;

    float acc[7];
    #pragma unroll
    for (int c = 0; c < 7; c++) acc[c] = ws[1496 + c];

    #pragma unroll 1
    for (int t = 0; t < 11; t++) {
        // coalesced x loads (3 LDG.32 per step)
        const float x0 = g_xT[(size_t)(t * 3 + 0) * B_TOTAL + e];
        const float x1 = g_xT[(size_t)(t * 3 + 1) * B_TOTAL + e];
        const float x2 = g_xT[(size_t)(t * 3 + 2) * B_TOTAL + e];

        float hn[11];
        const float* wd = ws + 528 + t * 88;

        #pragma unroll
        for (int j = 0; j < 11; j++) {
            const float* W = ws + j * 48;
            float az = W[0], ar = W[1], ah = W[2], bh = W[3];
            az = fmaf(x0, W[4],  az); az = fmaf(x1, W[5],  az); az = fmaf(x2, W[6],  az);
            ar = fmaf(x0, W[7],  ar); ar = fmaf(x1, W[8],  ar); ar = fmaf(x2, W[9],  ar);
            ah = fmaf(x0, W[10], ah); ah = fmaf(x1, W[11], ah); ah = fmaf(x2, W[12], ah);
            #pragma unroll
            for (int i = 0; i < 11; i++) {
                az = fmaf(h[i], W[14 + i], az);
                ar = fmaf(h[i], W[25 + i], ar);
                bh = fmaf(h[i], W[36 + i], bh);
            }
            float z  = sig1(az);
            float r  = sig1(ar);
            float hh = tnh1(fmaf(r, bh, ah));
            float nh = fmaf(z, h[j] - hh, hh);          // hh + z*(h-hh)
            hn[j] = nh;

            const float* wj = wd + j * 8;
            #pragma unroll
            for (int c = 0; c < 7; c++)
                acc[c] = fmaf(nh, wj[c], acc[c]);       // fused dense
        }
        #pragma unroll
        for (int i = 0; i < 11; i++) h[i] = hn[i];
    }

    // softmax + store
    float m = acc[0];
    #pragma unroll
    for (int c = 1; c < 7; c++) m = fmaxf(m, acc[c]);
    float ex[7], s = 0.0f;
    #pragma unroll
    for (int c = 0; c < 7; c++) { ex[c] = fex2((acc[c] - m) * LOG2E); s += ex[c]; }
    const float inv = frcp(s);
    float* o = out + (size_t)e * 7;
    #pragma unroll
    for (int c = 0; c < 7; c++) o[c] = ex[c] * inv;
}

// ---------------- launch ----------------
extern "C" void kernel_launch(void* const* d_in, const int* in_sizes, int n_in,
                              void* d_out, int out_size) {
    const float* x    = (const float*)d_in[0];   // [B, 11, 3]
    const float* K    = (const float*)d_in[1];   // [3, 33]
    const float* R    = (const float*)d_in[2];   // [11, 33]
    const float* bias = (const float*)d_in[3];   // [2, 33]
    const float* Wd   = (const float*)d_in[4];   // [121, 7]
    const float* db   = (const float*)d_in[5];   // [7]
    float* out = (float*)d_out;                  // [B, 7]

    xpose_kernel<<<B_TOTAL / TP_ELEMS, 256>>>(x, K, R, bias, Wd, db);
    gru_main<<<B_TOTAL / NTHREADS, NTHREADS>>>(out);
}

// round 8
// speedup vs baseline: 3.6552x; 1.2977x over previous
#include <cuda_runtime.h>

// ============================================================================
// RNN_29463475650831: GRU(T=11,F=3,H=11, reset_after) + Dense(121->7) + softmax
// B = 1,048,576. fp32. R8: 2 elements/thread with SCALAR registers.
// Weight LDS amortized over 2 elements; 2x ILP on FMA chains; LDG.64 x loads.
// 168-reg budget (3x128 thr/SM) — proven spill-free regime from R7.
// ============================================================================

#define NTHREADS 128
#define B_TOTAL 1048576
#define LOG2E 1.4426950408889634f

// Scalar weight image (floats): region A 48/j (11 j), D (528+), Db (1496+)
#define WTOTF 1504
__device__ __align__(16) float g_wimg[WTOTF];

// Transposed input: plane layout [t*3+f][elem]  (33 planes of B floats)
__device__ __align__(16) float g_xT[33u * B_TOTAL];   // 138 MB static scratch

// ---------------- scalar math helpers ----------------
static __device__ __forceinline__ float fex2(float x) {
    float y; asm("ex2.approx.f32 %0, %1;" : "=f"(y) : "f"(x)); return y;
}
static __device__ __forceinline__ float frcp(float x) {
    float y; asm("rcp.approx.f32 %0, %1;" : "=f"(y) : "f"(x)); return y;
}
static __device__ __forceinline__ float sig1(float a) {
    return frcp(1.0f + fex2(-LOG2E * a));     // sigmoid
}
static __device__ __forceinline__ float tnh1(float a) {
    return 1.0f - 2.0f * frcp(1.0f + fex2(2.0f * LOG2E * a));   // tanh
}

// ---------------- weight image builder ----------------
static __device__ __forceinline__ float wval(int i,
                                             const float* K, const float* R,
                                             const float* bias, const float* Wd,
                                             const float* db) {
    float v = 0.0f;
    if (i < 528) {
        int j = i / 48, k = i % 48;
        if      (k == 0)  v = bias[j]      + bias[33 + j];
        else if (k == 1)  v = bias[11 + j] + bias[44 + j];
        else if (k == 2)  v = bias[22 + j];
        else if (k == 3)  v = bias[55 + j];
        else if (k < 7)   v = K[(k - 4)  * 33 + j];
        else if (k < 10)  v = K[(k - 7)  * 33 + 11 + j];
        else if (k < 13)  v = K[(k - 10) * 33 + 22 + j];
        else if (k == 13) v = 0.0f;
        else if (k < 25)  v = R[(k - 14) * 33 + j];
        else if (k < 36)  v = R[(k - 25) * 33 + 11 + j];
        else if (k < 47)  v = R[(k - 36) * 33 + 22 + j];
    } else if (i < 1496) {
        int d = i - 528, c = d & 7;
        if (c < 7) v = Wd[(d >> 3) * 7 + c];
    } else {
        int c = i - 1496;
        if (c < 7) v = db[c];
    }
    return v;
}

// ---------------- kernel 1: transpose x + (block 0) build weight image ------
#define TP_ELEMS 256
__global__ __launch_bounds__(256)
void xpose_kernel(const float* __restrict__ x,
                  const float* __restrict__ K, const float* __restrict__ R,
                  const float* __restrict__ bias, const float* __restrict__ Wd,
                  const float* __restrict__ db) {
    __shared__ float tile[TP_ELEMS * 33];
    const unsigned base = blockIdx.x * (TP_ELEMS * 33u);
    #pragma unroll
    for (int k = 0; k < 33; k++) {
        int i = k * 256 + threadIdx.x;
        tile[i] = x[base + i];
    }
    if (blockIdx.x == 0) {
        for (int i = threadIdx.x; i < WTOTF; i += 256) {
            g_wimg[i] = wval(i, K, R, bias, Wd, db);
        }
    }
    __syncthreads();
    const unsigned ebase = blockIdx.x * TP_ELEMS;
    #pragma unroll 4
    for (int idx = threadIdx.x; idx < 33 * TP_ELEMS; idx += 256) {
        int plane = idx / TP_ELEMS;          // 0..32
        int el    = idx % TP_ELEMS;          // 0..255 -> coalesced write
        g_xT[(size_t)plane * B_TOTAL + ebase + el] = tile[el * 33 + plane];
    }
}

// ---------------- kernel 2: main GRU (scalar, 2 elems/thread) ---------------
__global__ __launch_bounds__(NTHREADS, 3)   // 168-reg budget (spill-free)
void gru_main(float* __restrict__ out) {
    __shared__ __align__(16) float ws[WTOTF];
    {
        const float4* s = reinterpret_cast<const float4*>(g_wimg);
        float4* d = reinterpret_cast<float4*>(ws);
        #pragma unroll
        for (int i = threadIdx.x; i < WTOTF / 4; i += NTHREADS) d[i] = s[i];
    }
    __syncthreads();

    const unsigned p = blockIdx.x * NTHREADS + threadIdx.x;   // pair index
    const unsigned e0 = 2u * p;                               // elements e0, e0+1

    float ha[11], hb[11];
    #pragma unroll
    for (int i = 0; i < 11; i++) { ha[i] = 0.0f; hb[i] = 0.0f; }

    float aca[7], acb[7];
    #pragma unroll
    for (int c = 0; c < 7; c++) { float b = ws[1496 + c]; aca[c] = b; acb[c] = b; }

    #pragma unroll 1
    for (int t = 0; t < 11; t++) {
        // coalesced LDG.64: adjacent elements within the plane
        const float2 X0 = *reinterpret_cast<const float2*>(&g_xT[(size_t)(t * 3 + 0) * B_TOTAL + e0]);
        const float2 X1 = *reinterpret_cast<const float2*>(&g_xT[(size_t)(t * 3 + 1) * B_TOTAL + e0]);
        const float2 X2 = *reinterpret_cast<const float2*>(&g_xT[(size_t)(t * 3 + 2) * B_TOTAL + e0]);

        float hna[11], hnb[11];
        const float* wd = ws + 528 + t * 88;

        #pragma unroll
        for (int j = 0; j < 11; j++) {
            const float* W = ws + j * 48;
            float w;
            w = W[0]; float aza = w, azb = w;
            w = W[1]; float ara = w, arb = w;
            w = W[2]; float aha = w, ahb = w;
            w = W[3]; float bha = w, bhb = w;
            w = W[4];  aza = fmaf(X0.x, w, aza); azb = fmaf(X0.y, w, azb);
            w = W[5];  aza = fmaf(X1.x, w, aza); azb = fmaf(X1.y, w, azb);
            w = W[6];  aza = fmaf(X2.x, w, aza); azb = fmaf(X2.y, w, azb);
            w = W[7];  ara = fmaf(X0.x, w, ara); arb = fmaf(X0.y, w, arb);
            w = W[8];  ara = fmaf(X1.x, w, ara); arb = fmaf(X1.y, w, arb);
            w = W[9];  ara = fmaf(X2.x, w, ara); arb = fmaf(X2.y, w, arb);
            w = W[10]; aha = fmaf(X0.x, w, aha); ahb = fmaf(X0.y, w, ahb);
            w = W[11]; aha = fmaf(X1.x, w, aha); ahb = fmaf(X1.y, w, ahb);
            w = W[12]; aha = fmaf(X2.x, w, aha); ahb = fmaf(X2.y, w, ahb);
            #pragma unroll
            for (int i = 0; i < 11; i++) {
                w = W[14 + i]; aza = fmaf(ha[i], w, aza); azb = fmaf(hb[i], w, azb);
                w = W[25 + i]; ara = fmaf(ha[i], w, ara); arb = fmaf(hb[i], w, arb);
                w = W[36 + i]; bha = fmaf(ha[i], w, bha); bhb = fmaf(hb[i], w, bhb);
            }
            float za  = sig1(aza),            zb  = sig1(azb);
            float ra  = sig1(ara),            rb  = sig1(arb);
            float hha = tnh1(fmaf(ra, bha, aha));
            float hhb = tnh1(fmaf(rb, bhb, ahb));
            float nha = fmaf(za, ha[j] - hha, hha);
            float nhb = fmaf(zb, hb[j] - hhb, hhb);
            hna[j] = nha; hnb[j] = nhb;

            const float* wj = wd + j * 8;
            #pragma unroll
            for (int c = 0; c < 7; c++) {
                w = wj[c];
                aca[c] = fmaf(nha, w, aca[c]);
                acb[c] = fmaf(nhb, w, acb[c]);
            }
        }
        #pragma unroll
        for (int i = 0; i < 11; i++) { ha[i] = hna[i]; hb[i] = hnb[i]; }
    }

    // softmax per element; write 14 floats as 7 float2 (56B contiguous)
    float r14[14];
    {
        float m = aca[0];
        #pragma unroll
        for (int c = 1; c < 7; c++) m = fmaxf(m, aca[c]);
        float ex[7], s = 0.0f;
        #pragma unroll
        for (int c = 0; c < 7; c++) { ex[c] = fex2((aca[c] - m) * LOG2E); s += ex[c]; }
        float inv = frcp(s);
        #pragma unroll
        for (int c = 0; c < 7; c++) r14[c] = ex[c] * inv;
    }
    {
        float m = acb[0];
        #pragma unroll
        for (int c = 1; c < 7; c++) m = fmaxf(m, acb[c]);
        float ex[7], s = 0.0f;
        #pragma unroll
        for (int c = 0; c < 7; c++) { ex[c] = fex2((acb[c] - m) * LOG2E); s += ex[c]; }
        float inv = frcp(s);
        #pragma unroll
        for (int c = 0; c < 7; c++) r14[7 + c] = ex[c] * inv;
    }
    float2* o2 = reinterpret_cast<float2*>(out) + (size_t)p * 7;
    #pragma unroll
    for (int q = 0; q < 7; q++) o2[q] = make_float2(r14[2 * q], r14[2 * q + 1]);
}

// ---------------- launch ----------------
extern "C" void kernel_launch(void* const* d_in, const int* in_sizes, int n_in,
                              void* d_out, int out_size) {
    const float* x    = (const float*)d_in[0];   // [B, 11, 3]
    const float* K    = (const float*)d_in[1];   // [3, 33]
    const float* R    = (const float*)d_in[2];   // [11, 33]
    const float* bias = (const float*)d_in[3];   // [2, 33]
    const float* Wd   = (const float*)d_in[4];   // [121, 7]
    const float* db   = (const float*)d_in[5];   // [7]
    float* out = (float*)d_out;                  // [B, 7]

    xpose_kernel<<<B_TOTAL / TP_ELEMS, 256>>>(x, K, R, bias, Wd, db);
    gru_main<<<(B_TOTAL / 2) / NTHREADS, NTHREADS>>>(out);
}

// round 10
// speedup vs baseline: 5.3999x; 1.4773x over previous
#include <cuda_runtime.h>

// ============================================================================
// RNN_29463475650831: GRU(T=11,F=3,H=11, reset_after) + Dense(121->7) + softmax
// B = 1,048,576. fp32. R9: 4 elements/thread (scalar regs, 255-reg budget,
// 2 blocks/SM), MUFU.TANH activations, LDG.128 x loads, STG.128 stores.
// ============================================================================

#define NTHREADS 128
#define B_TOTAL 1048576
#define LOG2E 1.4426950408889634f

// Scalar weight image (floats): region A 48/j (11 j), D (528+), Db (1496+)
#define WTOTF 1504
__device__ __align__(16) float g_wimg[WTOTF];

// Transposed input: plane layout [t*3+f][elem]  (33 planes of B floats)
__device__ __align__(16) float g_xT[33u * B_TOTAL];   // 138 MB static scratch

// ---------------- scalar math helpers ----------------
static __device__ __forceinline__ float fex2(float x) {
    float y; asm("ex2.approx.f32 %0, %1;" : "=f"(y) : "f"(x)); return y;
}
static __device__ __forceinline__ float frcp(float x) {
    float y; asm("rcp.approx.f32 %0, %1;" : "=f"(y) : "f"(x)); return y;
}
static __device__ __forceinline__ float tnh1(float x) {       // MUFU.TANH
    float y; asm("tanh.approx.f32 %0, %1;" : "=f"(y) : "f"(x)); return y;
}
static __device__ __forceinline__ float sig1(float a) {       // 0.5+0.5*tanh(a/2)
    return fmaf(0.5f, tnh1(0.5f * a), 0.5f);
}

// ---------------- weight image builder ----------------
static __device__ __forceinline__ float wval(int i,
                                             const float* K, const float* R,
                                             const float* bias, const float* Wd,
                                             const float* db) {
    float v = 0.0f;
    if (i < 528) {
        int j = i / 48, k = i % 48;
        if      (k == 0)  v = bias[j]      + bias[33 + j];
        else if (k == 1)  v = bias[11 + j] + bias[44 + j];
        else if (k == 2)  v = bias[22 + j];
        else if (k == 3)  v = bias[55 + j];
        else if (k < 7)   v = K[(k - 4)  * 33 + j];
        else if (k < 10)  v = K[(k - 7)  * 33 + 11 + j];
        else if (k < 13)  v = K[(k - 10) * 33 + 22 + j];
        else if (k == 13) v = 0.0f;
        else if (k < 25)  v = R[(k - 14) * 33 + j];
        else if (k < 36)  v = R[(k - 25) * 33 + 11 + j];
        else if (k < 47)  v = R[(k - 36) * 33 + 22 + j];
    } else if (i < 1496) {
        int d = i - 528, c = d & 7;
        if (c < 7) v = Wd[(d >> 3) * 7 + c];
    } else {
        int c = i - 1496;
        if (c < 7) v = db[c];
    }
    return v;
}

// ---------------- kernel 1: transpose x + (block 0) build weight image ------
#define TP_ELEMS 256
__global__ __launch_bounds__(256)
void xpose_kernel(const float* __restrict__ x,
                  const float* __restrict__ K, const float* __restrict__ R,
                  const float* __restrict__ bias, const float* __restrict__ Wd,
                  const float* __restrict__ db) {
    __shared__ float tile[TP_ELEMS * 33];
    const unsigned base = blockIdx.x * (TP_ELEMS * 33u);
    #pragma unroll
    for (int k = 0; k < 33; k++) {
        int i = k * 256 + threadIdx.x;
        tile[i] = x[base + i];
    }
    if (blockIdx.x == 0) {
        for (int i = threadIdx.x; i < WTOTF; i += 256) {
            g_wimg[i] = wval(i, K, R, bias, Wd, db);
        }
    }
    __syncthreads();
    const unsigned ebase = blockIdx.x * TP_ELEMS;
    #pragma unroll 4
    for (int idx = threadIdx.x; idx < 33 * TP_ELEMS; idx += 256) {
        int plane = idx / TP_ELEMS;          // 0..32
        int el    = idx % TP_ELEMS;          // 0..255 -> coalesced write
        g_xT[(size_t)plane * B_TOTAL + ebase + el] = tile[el * 33 + plane];
    }
}

// ---------------- kernel 2: main GRU (scalar, 4 elems/thread) ---------------
__global__ __launch_bounds__(NTHREADS, 2)   // 255-reg budget
void gru_main(float* __restrict__ out) {
    __shared__ __align__(16) float ws[WTOTF];
    {
        const float4* s = reinterpret_cast<const float4*>(g_wimg);
        float4* d = reinterpret_cast<float4*>(ws);
        #pragma unroll
        for (int i = threadIdx.x; i < WTOTF / 4; i += NTHREADS) d[i] = s[i];
    }
    __syncthreads();

    const unsigned q = blockIdx.x * NTHREADS + threadIdx.x;   // quad index
    const unsigned e0 = 4u * q;                               // elements e0..e0+3

    float ha[11], hb[11], hc[11], hd[11];
    #pragma unroll
    for (int i = 0; i < 11; i++) { ha[i] = hb[i] = hc[i] = hd[i] = 0.0f; }

    float aca[7], acb[7], acc_[7], acd[7];
    #pragma unroll
    for (int c = 0; c < 7; c++) {
        float b = ws[1496 + c];
        aca[c] = b; acb[c] = b; acc_[c] = b; acd[c] = b;
    }

    #pragma unroll 1
    for (int t = 0; t < 11; t++) {
        // coalesced LDG.128: 4 adjacent elements within each plane
        const float4 X0 = *reinterpret_cast<const float4*>(&g_xT[(size_t)(t * 3 + 0) * B_TOTAL + e0]);
        const float4 X1 = *reinterpret_cast<const float4*>(&g_xT[(size_t)(t * 3 + 1) * B_TOTAL + e0]);
        const float4 X2 = *reinterpret_cast<const float4*>(&g_xT[(size_t)(t * 3 + 2) * B_TOTAL + e0]);

        float hna[11], hnb[11], hnc[11], hnd[11];
        const float* wd = ws + 528 + t * 88;

        #pragma unroll
        for (int j = 0; j < 11; j++) {
            const float* W = ws + j * 48;
            float w;
            w = W[0]; float aza = w, azb = w, azc = w, azd = w;
            w = W[1]; float ara = w, arb = w, arc = w, ard = w;
            w = W[2]; float aha = w, ahb = w, ahc = w, ahd = w;
            w = W[3]; float bha = w, bhb = w, bhc = w, bhd = w;
            w = W[4];  aza = fmaf(X0.x, w, aza); azb = fmaf(X0.y, w, azb);
                       azc = fmaf(X0.z, w, azc); azd = fmaf(X0.w, w, azd);
            w = W[5];  aza = fmaf(X1.x, w, aza); azb = fmaf(X1.y, w, azb);
                       azc = fmaf(X1.z, w, azc); azd = fmaf(X1.w, w, azd);
            w = W[6];  aza = fmaf(X2.x, w, aza); azb = fmaf(X2.y, w, azb);
                       azc = fmaf(X2.z, w, azc); azd = fmaf(X2.w, w, azd);
            w = W[7];  ara = fmaf(X0.x, w, ara); arb = fmaf(X0.y, w, arb);
                       arc = fmaf(X0.z, w, arc); ard = fmaf(X0.w, w, ard);
            w = W[8];  ara = fmaf(X1.x, w, ara); arb = fmaf(X1.y, w, arb);
                       arc = fmaf(X1.z, w, arc); ard = fmaf(X1.w, w, ard);
            w = W[9];  ara = fmaf(X2.x, w, ara); arb = fmaf(X2.y, w, arb);
                       arc = fmaf(X2.z, w, arc); ard = fmaf(X2.w, w, ard);
            w = W[10]; aha = fmaf(X0.x, w, aha); ahb = fmaf(X0.y, w, ahb);
                       ahc = fmaf(X0.z, w, ahc); ahd = fmaf(X0.w, w, ahd);
            w = W[11]; aha = fmaf(X1.x, w, aha); ahb = fmaf(X1.y, w, ahb);
                       ahc = fmaf(X1.z, w, ahc); ahd = fmaf(X1.w, w, ahd);
            w = W[12]; aha = fmaf(X2.x, w, aha); ahb = fmaf(X2.y, w, ahb);
                       ahc = fmaf(X2.z, w, ahc); ahd = fmaf(X2.w, w, ahd);
            #pragma unroll
            for (int i = 0; i < 11; i++) {
                w = W[14 + i];
                aza = fmaf(ha[i], w, aza); azb = fmaf(hb[i], w, azb);
                azc = fmaf(hc[i], w, azc); azd = fmaf(hd[i], w, azd);
                w = W[25 + i];
                ara = fmaf(ha[i], w, ara); arb = fmaf(hb[i], w, arb);
                arc = fmaf(hc[i], w, arc); ard = fmaf(hd[i], w, ard);
                w = W[36 + i];
                bha = fmaf(ha[i], w, bha); bhb = fmaf(hb[i], w, bhb);
                bhc = fmaf(hc[i], w, bhc); bhd = fmaf(hd[i], w, bhd);
            }
            float za = sig1(aza), zb = sig1(azb), zc = sig1(azc), zd = sig1(azd);
            float ra = sig1(ara), rb = sig1(arb), rc = sig1(arc), rd = sig1(ard);
            float hha = tnh1(fmaf(ra, bha, aha));
            float hhb = tnh1(fmaf(rb, bhb, ahb));
            float hhc = tnh1(fmaf(rc, bhc, ahc));
            float hhd = tnh1(fmaf(rd, bhd, ahd));
            float nha = fmaf(za, ha[j] - hha, hha);
            float nhb = fmaf(zb, hb[j] - hhb, hhb);
            float nhc = fmaf(zc, hc[j] - hhc, hhc);
            float nhd = fmaf(zd, hd[j] - hhd, hhd);
            hna[j] = nha; hnb[j] = nhb; hnc[j] = nhc; hnd[j] = nhd;

            const float* wj = wd + j * 8;
            #pragma unroll
            for (int c = 0; c < 7; c++) {
                w = wj[c];
                aca[c]  = fmaf(nha, w, aca[c]);
                acb[c]  = fmaf(nhb, w, acb[c]);
                acc_[c] = fmaf(nhc, w, acc_[c]);
                acd[c]  = fmaf(nhd, w, acd[c]);
            }
        }
        #pragma unroll
        for (int i = 0; i < 11; i++) {
            ha[i] = hna[i]; hb[i] = hnb[i]; hc[i] = hnc[i]; hd[i] = hnd[i];
        }
    }

    // softmax per element; 28 contiguous floats -> 7 aligned STG.128
    float r28[28];
    {
        const float* A[4] = { aca, acb, acc_, acd };
        #pragma unroll
        for (int v = 0; v < 4; v++) {
            const float* a = A[v];
            float m = a[0];
            #pragma unroll
            for (int c = 1; c < 7; c++) m = fmaxf(m, a[c]);
            float ex[7], s = 0.0f;
            #pragma unroll
            for (int c = 0; c < 7; c++) { ex[c] = fex2((a[c] - m) * LOG2E); s += ex[c]; }
            float inv = frcp(s);
            #pragma unroll
            for (int c = 0; c < 7; c++) r28[v * 7 + c] = ex[c] * inv;
        }
    }
    float4* o4 = reinterpret_cast<float4*>(out + (size_t)e0 * 7);   // 112B, 16B-aligned
    #pragma unroll
    for (int k = 0; k < 7; k++)
        o4[k] = make_float4(r28[4 * k], r28[4 * k + 1], r28[4 * k + 2], r28[4 * k + 3]);
}

// ---------------- launch ----------------
extern "C" void kernel_launch(void* const* d_in, const int* in_sizes, int n_in,
                              void* d_out, int out_size) {
    const float* x    = (const float*)d_in[0];   // [B, 11, 3]
    const float* K    = (const float*)d_in[1];   // [3, 33]
    const float* R    = (const float*)d_in[2];   // [11, 33]
    const float* bias = (const float*)d_in[3];   // [2, 33]
    const float* Wd   = (const float*)d_in[4];   // [121, 7]
    const float* db   = (const float*)d_in[5];   // [7]
    float* out = (float*)d_out;                  // [B, 7]

    xpose_kernel<<<B_TOTAL / TP_ELEMS, 256>>>(x, K, R, bias, Wd, db);
    gru_main<<<(B_TOTAL / 4) / NTHREADS, NTHREADS>>>(out);
}